// round 7
// baseline (speedup 1.0000x reference)
#include <cuda_runtime.h>
#include <cuda_fp16.h>
#include <math.h>
#include <stdint.h>

// Problem constants
#define L 4096
#define H 32
#define EP 32
#define EPH 1024
#define KTAP 4
#define NCH 1024
#define CHUNKS 32
#define CHUNK_LEN 128
#define KTOT 4096          // effective GEMM K = KTAP * EPH

// ---------------- scratch (device globals) ----------------
__device__ __half g_ApadHi[(L + 3) * EPH];   // padded tap-shift A, fp16 hi
__device__ __half g_ApadLo[(L + 3) * EPH];   // fp16 lo (residual)
__device__ __half g_WT    [EPH * KTOT];      // conv weights transposed [o][kk], fp16
__device__ float  g_Lam  [L * EPH];
__device__ float  g_Bact [L * EPH];
__device__ float2 g_A    [L * NCH];
__device__ float2 g_Bu   [L * NCH];
__device__ float2 g_xs   [L * NCH];
__device__ float  g_ys   [L * H];
__device__ float4 g_agg  [CHUNKS * NCH];
__device__ float2 g_carry[CHUNKS * NCH];
__device__ float2 g_A0   [NCH];
__device__ float2 g_Bc   [NCH];

__device__ __forceinline__ float siluf(float v) {
    return v / (1.0f + expf(-v));
}

__device__ __forceinline__ uint32_t smem_u32(const void* p) {
    uint32_t a;
    asm("{ .reg .u64 t; cvta.to.shared.u64 t, %1; cvt.u32.u64 %0, t; }" : "=r"(a) : "l"(p));
    return a;
}

#define CP_ASYNC16(dst, src) \
    asm volatile("cp.async.cg.shared.global [%0], [%1], 16;" :: "r"(dst), "l"(src))
#define CP_COMMIT() asm volatile("cp.async.commit_group;" ::: "memory")
#define CP_WAIT1()  asm volatile("cp.async.wait_group 1;" ::: "memory")

__device__ __forceinline__ void ldm_x4(uint32_t* r, uint32_t addr) {
    asm volatile("ldmatrix.sync.aligned.m8n8.x4.shared.b16 {%0,%1,%2,%3}, [%4];"
                 : "=r"(r[0]), "=r"(r[1]), "=r"(r[2]), "=r"(r[3]) : "r"(addr));
}

__device__ __forceinline__ void mma16816(float* c, const uint32_t* a,
                                         uint32_t b0, uint32_t b1) {
    asm volatile(
        "mma.sync.aligned.m16n8k16.row.col.f32.f16.f16.f32 "
        "{%0,%1,%2,%3}, {%4,%5,%6,%7}, {%8,%9}, {%0,%1,%2,%3};"
        : "+f"(c[0]), "+f"(c[1]), "+f"(c[2]), "+f"(c[3])
        : "r"(a[0]), "r"(a[1]), "r"(a[2]), "r"(a[3]), "r"(b0), "r"(b1));
}

// ---------------- K0: precompute A0, Bc + zero pad rows --------------------------
__global__ void precompute_kernel(const float* __restrict__ Lre,
                                  const float* __restrict__ Lim,
                                  const float* __restrict__ logstep) {
    int c = threadIdx.x;
    int h = c >> 5;
    float st = expf(logstep[h]);
    float lr = Lre[c], li = Lim[c];
    float zr = lr * st, zi = li * st;
    float e  = expf(zr);
    float a0r = e * cosf(zi);
    float a0i = e * sinf(zi);
    float nr = a0r - 1.0f, ni = a0i;
    float inv = 1.0f / (lr * lr + li * li);
    g_A0[c] = make_float2(a0r, a0i);
    g_Bc[c] = make_float2((nr * lr + ni * li) * inv, (ni * lr - nr * li) * inv);

    __half z = __float2half(0.0f);
    g_ApadHi[0 * EPH + c] = z;               g_ApadLo[0 * EPH + c] = z;
    g_ApadHi[(L + 1) * EPH + c] = z;         g_ApadLo[(L + 1) * EPH + c] = z;
    g_ApadHi[(L + 2) * EPH + c] = z;         g_ApadLo[(L + 2) * EPH + c] = z;
}

// ---------------- K1: B_proj (fp16 hi/lo into padded buf) ; Lam = silu(x@Wl) -----
__global__ __launch_bounds__(256) void proj_kernel(const float* __restrict__ x,
                                                   const float* __restrict__ Wb,
                                                   const float* __restrict__ bb,
                                                   const float* __restrict__ Wl,
                                                   const float* __restrict__ bl) {
    __shared__ float xsm[32][33];
    int lb = blockIdx.x * 32;
    int t  = threadIdx.x;
    for (int i = t; i < 32 * 32; i += 256) {
        int r = i >> 5, h = i & 31;
        xsm[r][h] = x[(lb + r) * H + h];
    }
    __syncthreads();

    for (int j = 0; j < 4; j++) {
        int o = t + j * 256;
        {
            float wcol[32];
            #pragma unroll
            for (int h = 0; h < 32; h++) wcol[h] = Wb[h * EPH + o];
            float bv = bb[o];
            for (int r = 0; r < 32; r++) {
                float acc = bv;
                #pragma unroll
                for (int h = 0; h < 32; h++) acc += xsm[r][h] * wcol[h];
                __half hi = __float2half(acc);
                float lof = acc - __half2float(hi);
                int row = lb + r + 1;  // padded offset
                g_ApadHi[row * EPH + o] = hi;
                g_ApadLo[row * EPH + o] = __float2half(lof);
            }
        }
        {
            float wcol[32];
            #pragma unroll
            for (int h = 0; h < 32; h++) wcol[h] = Wl[h * EPH + o];
            float bv = bl[o];
            for (int r = 0; r < 32; r++) {
                float acc = bv;
                #pragma unroll
                for (int h = 0; h < 32; h++) acc += xsm[r][h] * wcol[h];
                g_Lam[(lb + r) * EPH + o] = siluf(acc);
            }
        }
    }
}

// ---------------- K1b: transpose conv weights to [o][kk] fp16 --------------------
__global__ __launch_bounds__(256) void wtrans_kernel(const float* __restrict__ cw) {
    __shared__ float tile[32][33];
    int k0 = blockIdx.x * 32;
    int o0 = blockIdx.y * 32;
    int t = threadIdx.x;
    int r = t >> 5, c = t & 31;
    #pragma unroll
    for (int rr = r; rr < 32; rr += 8)
        tile[rr][c] = cw[(size_t)(k0 + rr) * EPH + o0 + c];
    __syncthreads();
    #pragma unroll
    for (int rr = r; rr < 32; rr += 8) {
        float v = tile[c][rr];
        size_t idx = (size_t)(o0 + rr) * KTOT + k0 + c;
        g_WT[idx] = __float2half(v);
    }
}

// ---------------- K2: conv GEMM via mma.sync fp16 (2-product split) --------------
// CTA tile 128(m=l) x 256(n=o), BK=32, 16 warps (4 m x 4 n), warp tile 32x64.
// acc += AHi*W + ALo*W (W single fp16; fp32 accumulators)
// 3-stage cp.async pipeline; grid = 32x4 = 128 CTAs = one full wave.
#define GM 128
#define GN 256
#define GK 32
#define NCHUNK (KTOT / GK)        // 128
#define ROWB 80                   // smem row stride bytes (32 fp16 = 64B + pad)
#define ATILE_B (128 * ROWB)      // 10240
#define WTILE_B (256 * ROWB)      // 20480
#define BUF_B (2 * ATILE_B + WTILE_B)  // 40960
#define STAGES 3
#define CONV_SMEM (STAGES * BUF_B)     // 122880

__global__ __launch_bounds__(512, 1)
void conv_mma_kernel(const float* __restrict__ cb) {
    extern __shared__ char smem[];
    uint32_t sbase = smem_u32(smem);
    int t = threadIdx.x;
    int lane = t & 31;
    int wid = t >> 5;                 // 0..15
    int warp_m = wid & 3;             // 4 warps in m
    int warp_n = wid >> 2;            // 4 warps in n
    int lb = blockIdx.x * GM;
    int nb = blockIdx.y * GN;

    float acc[2][8][4];
    #pragma unroll
    for (int i = 0; i < 2; i++)
        #pragma unroll
        for (int j = 0; j < 8; j++)
            #pragma unroll
            for (int k = 0; k < 4; k++) acc[i][j][k] = 0.0f;

    // load mappings (512 threads):
    // W: row = t>>1 (256 rows), half = t&1 -> 32 bytes each
    int wrow = t >> 1;
    int whalf = t & 1;
    uint32_t dWpos = wrow * ROWB + whalf * 32;
    // A: sel = t>>8 (0=hi,1=lo), row = (t&255)>>1, half = t&1
    int asel = t >> 8;
    int arow = (t & 255) >> 1;
    uint32_t dApos = arow * ROWB + whalf * 32;

    auto issue = [&](int kc) {
        uint32_t base = sbase + (kc % 3) * BUF_B;
        int kg = kc * GK;
        int tap = kg >> 10;
        int i0 = kg & 1023;
        {
            const __half* src = asel ? g_ApadLo : g_ApadHi;
            size_t go = (size_t)(lb + arow + tap) * EPH + i0 + whalf * 16;
            const char* sp = (const char*)(src + go);
            uint32_t d = base + asel * ATILE_B + dApos;
            CP_ASYNC16(d,      sp);
            CP_ASYNC16(d + 16, sp + 16);
        }
        {
            size_t go = (size_t)(nb + wrow) * KTOT + kg + whalf * 16;
            const char* sw = (const char*)(g_WT + go);
            uint32_t d = base + 2 * ATILE_B + dWpos;
            CP_ASYNC16(d,      sw);
            CP_ASYNC16(d + 16, sw + 16);
        }
    };

    // ldmatrix lane mapping
    int lr8 = lane & 7;
    int lsel = lane >> 3;             // 0..3
    int lmn = (lsel & 1) * 8 + lr8;   // row within 16
    int lk8 = (lsel >> 1) * 8;        // k offset 0/8

    issue(0); CP_COMMIT();
    issue(1); CP_COMMIT();

    for (int kc = 0; kc < NCHUNK; kc++) {
        CP_WAIT1();
        __syncthreads();
        if (kc + 2 < NCHUNK) issue(kc + 2);
        CP_COMMIT();

        uint32_t base = sbase + (kc % 3) * BUF_B;
        uint32_t Ah = base;
        uint32_t Al = base + ATILE_B;
        uint32_t Wt = base + 2 * ATILE_B;

        #pragma unroll
        for (int ks = 0; ks < 2; ks++) {
            int kbyte = (ks * 16 + lk8) * 2;
            uint32_t ah[2][4], al[2][4];
            #pragma unroll
            for (int im = 0; im < 2; im++) {
                uint32_t ro = (warp_m * 32 + im * 16 + lmn) * ROWB + kbyte;
                ldm_x4(ah[im], Ah + ro);
                ldm_x4(al[im], Al + ro);
            }
            uint32_t w[4][4];
            #pragma unroll
            for (int in4 = 0; in4 < 4; in4++) {
                uint32_t ro = (warp_n * 64 + in4 * 16 + lmn) * ROWB + kbyte;
                ldm_x4(w[in4], Wt + ro);
            }
            // product group 1: hi*W (16 independent MMAs)
            #pragma unroll
            for (int in4 = 0; in4 < 4; in4++)
                #pragma unroll
                for (int im = 0; im < 2; im++) {
                    mma16816(acc[im][in4 * 2 + 0], ah[im], w[in4][0], w[in4][2]);
                    mma16816(acc[im][in4 * 2 + 1], ah[im], w[in4][1], w[in4][3]);
                }
            // product group 2: lo*W
            #pragma unroll
            for (int in4 = 0; in4 < 4; in4++)
                #pragma unroll
                for (int im = 0; im < 2; im++) {
                    mma16816(acc[im][in4 * 2 + 0], al[im], w[in4][0], w[in4][2]);
                    mma16816(acc[im][in4 * 2 + 1], al[im], w[in4][1], w[in4][3]);
                }
        }
    }

    // epilogue: bias + silu, write fp32
    int gid = lane >> 2;
    int tig = lane & 3;
    #pragma unroll
    for (int im = 0; im < 2; im++) {
        int r0 = lb + warp_m * 32 + im * 16 + gid;
        #pragma unroll
        for (int j = 0; j < 8; j++) {
            int col = nb + warp_n * 64 + j * 8 + tig * 2;
            float b0 = cb[col], b1 = cb[col + 1];
            g_Bact[(size_t)r0 * EPH + col]           = siluf(acc[im][j][0] + b0);
            g_Bact[(size_t)r0 * EPH + col + 1]       = siluf(acc[im][j][1] + b1);
            g_Bact[(size_t)(r0 + 8) * EPH + col]     = siluf(acc[im][j][2] + b0);
            g_Bact[(size_t)(r0 + 8) * EPH + col + 1] = siluf(acc[im][j][3] + b1);
        }
    }
}

// ---------------- K3: elementwise A / Bu (high parallelism) ----------------------
__global__ __launch_bounds__(1024) void elemwise_kernel(const float* __restrict__ B) {
    int l = blockIdx.x;
    int c = threadIdx.x;
    int idx = l * NCH + c;
    float lam = g_Lam[idx];
    float ba  = g_Bact[idx];
    float2 a0 = g_A0[c];
    float2 bc = g_Bc[c];

    float zr = a0.x + lam;
    float zi = a0.y;
    float e  = expf(zr);
    float wr = 1.0f + e * cosf(zi);
    float wi = e * sinf(zi);
    float Ar = 0.5f * logf(wr * wr + wi * wi);
    float Ai = atan2f(wi, wr);

    int ep = c & 31;
    float br = B[l * (2 * EP) + ep * 2 + 0];
    float bi = B[l * (2 * EP) + ep * 2 + 1];
    float bur = (bc.x * br - bc.y * bi) * ba;
    float bui = (bc.x * bi + bc.y * br) * ba;

    g_A [idx] = make_float2(Ar, Ai);
    g_Bu[idx] = make_float2(bur, bui);
}

// ---------------- K4/K5/K6: chunked complex scan ---------------------------------
__global__ __launch_bounds__(256) void scan_p1_kernel() {
    int t = blockIdx.x * blockDim.x + threadIdx.x;
    int c = t & (NCH - 1);
    int ch = t >> 10;
    int base = ch * CHUNK_LEN;
    float Pr = 1.0f, Pi = 0.0f, sr = 0.0f, si = 0.0f;
    #pragma unroll 4
    for (int i = 0; i < CHUNK_LEN; i++) {
        float2 a = g_A [(base + i) * NCH + c];
        float2 b = g_Bu[(base + i) * NCH + c];
        float nsr = a.x * sr - a.y * si + b.x;
        float nsi = a.x * si + a.y * sr + b.y;
        sr = nsr; si = nsi;
        float npr = a.x * Pr - a.y * Pi;
        float npi = a.x * Pi + a.y * Pr;
        Pr = npr; Pi = npi;
    }
    g_agg[ch * NCH + c] = make_float4(Pr, Pi, sr, si);
}

__global__ __launch_bounds__(1024) void scan_p2_kernel() {
    int c = threadIdx.x;
    float cr = 0.0f, ci = 0.0f;
    #pragma unroll
    for (int ch = 0; ch < CHUNKS; ch++) {
        g_carry[ch * NCH + c] = make_float2(cr, ci);
        float4 g = g_agg[ch * NCH + c];
        float nr = g.x * cr - g.y * ci + g.z;
        float ni = g.x * ci + g.y * cr + g.w;
        cr = nr; ci = ni;
    }
}

__global__ __launch_bounds__(256) void scan_p3_kernel() {
    int t = blockIdx.x * blockDim.x + threadIdx.x;
    int c = t & (NCH - 1);
    int ch = t >> 10;
    int base = ch * CHUNK_LEN;
    float2 st = g_carry[ch * NCH + c];
    float xr = st.x, xi = st.y;
    #pragma unroll 4
    for (int i = 0; i < CHUNK_LEN; i++) {
        float2 a = g_A [(base + i) * NCH + c];
        float2 b = g_Bu[(base + i) * NCH + c];
        float nxr = a.x * xr - a.y * xi + b.x;
        float nxi = a.x * xi + a.y * xr + b.y;
        xr = nxr; xi = nxi;
        g_xs[(base + i) * NCH + c] = make_float2(xr, xi);
    }
}

// ---------------- K7: ys ---------------------------------------------------------
__global__ __launch_bounds__(256) void ys_kernel(const float* __restrict__ C) {
    int t = threadIdx.x;
    int lane = t & 31;
    int w = t >> 5;
    int l = blockIdx.x * 8 + w;
    const float2* xs = g_xs + (size_t)l * NCH;
    float acc = 0.0f;
    #pragma unroll
    for (int p = 0; p < 32; p++) {
        float cr = C[l * (2 * EP) + p * 2 + 0];
        float ci = C[l * (2 * EP) + p * 2 + 1];
        float2 v = xs[p * 32 + lane];
        acc += cr * v.x - ci * v.y;
    }
    g_ys[l * H + lane] = acc;
}

// ---------------- K8: gating + output projection ---------------------------------
__global__ __launch_bounds__(256) void final_kernel(const float* __restrict__ x,
                                                    const float* __restrict__ Wg,
                                                    const float* __restrict__ bg,
                                                    const float* __restrict__ Wd,
                                                    const float* __restrict__ bd,
                                                    const float* __restrict__ Wo,
                                                    const float* __restrict__ bo,
                                                    float* __restrict__ out) {
    __shared__ float sWg[H * H], sWo[H * H];
    __shared__ float sWd[H], sbg[H], sbo[H];
    __shared__ float sx[8][H], sht[8][H];
    int t = threadIdx.x;
    for (int i = t; i < H * H; i += 256) { sWg[i] = Wg[i]; sWo[i] = Wo[i]; }
    if (t < H) { sWd[t] = Wd[t]; sbg[t] = bg[t]; sbo[t] = bo[t]; }
    int lane = t & 31;
    int w = t >> 5;
    int l = blockIdx.x * 8 + w;
    sx[w][lane] = x[l * H + lane];
    __syncthreads();

    float xg = 0.0f, xd = 0.0f;
    #pragma unroll
    for (int h = 0; h < H; h++) {
        float xv = sx[w][h];
        xg += xv * sWg[h * H + lane];
        xd += xv * sWd[h];
    }
    float gt = siluf(xg + sbg[lane]);
    float d  = log1pf(expf(xd + bd[0]));
    float ysv = g_ys[l * H + lane];
    float xv  = sx[w][lane];
    float ht = (1.0f - gt) * (ysv + d * xv) + gt * xv;
    sht[w][lane] = ht;
    __syncwarp();

    float o = 0.0f;
    #pragma unroll
    for (int h = 0; h < H; h++) o += sht[w][h] * sWo[h * H + lane];
    out[l * H + lane] = o + sbo[lane];
}

// ---------------- launcher -------------------------------------------------------
extern "C" void kernel_launch(void* const* d_in, const int* in_sizes, int n_in,
                              void* d_out, int out_size) {
    const float* x       = (const float*)d_in[0];
    const float* Lre     = (const float*)d_in[1];
    const float* Lim     = (const float*)d_in[2];
    const float* B       = (const float*)d_in[3];
    const float* C       = (const float*)d_in[4];
    const float* logstep = (const float*)d_in[5];
    const float* Wb      = (const float*)d_in[6];
    const float* bb      = (const float*)d_in[7];
    const float* Wl      = (const float*)d_in[8];
    const float* bl      = (const float*)d_in[9];
    const float* cw      = (const float*)d_in[10];
    const float* cb      = (const float*)d_in[11];
    const float* Wg      = (const float*)d_in[12];
    const float* bg      = (const float*)d_in[13];
    const float* Wd      = (const float*)d_in[14];
    const float* bd      = (const float*)d_in[15];
    const float* Wo      = (const float*)d_in[16];
    const float* bo      = (const float*)d_in[17];
    float* out = (float*)d_out;

    static bool attr_set = false;
    if (!attr_set) {
        cudaFuncSetAttribute(conv_mma_kernel,
                             cudaFuncAttributeMaxDynamicSharedMemorySize, CONV_SMEM);
        attr_set = true;
    }

    // launch order keeps conv_mma_kernel at captured-profile index 3
    precompute_kernel<<<1, 1024>>>(Lre, Lim, logstep);
    proj_kernel<<<L / 32, 256>>>(x, Wb, bb, Wl, bl);

    dim3 wgrid(KTOT / 32, EPH / 32);          // (128, 32)
    wtrans_kernel<<<wgrid, 256>>>(cw);

    dim3 cgrid(L / GM, EPH / GN);             // (32, 4) = 128 CTAs = 1 wave
    conv_mma_kernel<<<cgrid, 512, CONV_SMEM>>>(cb);

    elemwise_kernel<<<L, 1024>>>(B);

    scan_p1_kernel<<<(CHUNKS * NCH) / 256, 256>>>();
    scan_p2_kernel<<<1, 1024>>>();
    scan_p3_kernel<<<(CHUNKS * NCH) / 256, 256>>>();

    ys_kernel<<<L / 8, 256>>>(C);
    final_kernel<<<L / 8, 256>>>(x, Wg, bg, Wd, bd, Wo, bo, out);
}

// round 8
// speedup vs baseline: 2.0041x; 2.0041x over previous
#include <cuda_runtime.h>
#include <cuda_fp16.h>
#include <math.h>
#include <stdint.h>

// Problem constants
#define L 4096
#define H 32
#define EP 32
#define EPH 1024
#define KTAP 4
#define NCH 1024
#define CHUNKS 32
#define CHUNK_LEN 128
#define KTOT 4096          // effective GEMM K = KTAP * EPH

// ---------------- scratch (device globals) ----------------
__device__ __half g_Apad[(L + 3) * EPH];     // padded tap-shift A, fp16
__device__ __half g_WT  [EPH * KTOT];        // conv weights transposed [o][kk], fp16
__device__ float  g_Lam  [L * EPH];
__device__ float  g_Bact [L * EPH];
__device__ float2 g_A    [L * NCH];
__device__ float2 g_Bu   [L * NCH];
__device__ float2 g_xs   [L * NCH];
__device__ float  g_ys   [L * H];
__device__ float4 g_agg  [CHUNKS * NCH];
__device__ float2 g_carry[CHUNKS * NCH];
__device__ float2 g_A0   [NCH];
__device__ float2 g_Bc   [NCH];

__device__ __forceinline__ float siluf(float v) {
    return v / (1.0f + expf(-v));
}

__device__ __forceinline__ uint32_t smem_u32(const void* p) {
    uint32_t a;
    asm("{ .reg .u64 t; cvta.to.shared.u64 t, %1; cvt.u32.u64 %0, t; }" : "=r"(a) : "l"(p));
    return a;
}

#define CP_ASYNC16(dst, src) \
    asm volatile("cp.async.cg.shared.global [%0], [%1], 16;" :: "r"(dst), "l"(src))
#define CP_COMMIT() asm volatile("cp.async.commit_group;" ::: "memory")
#define CP_WAIT2()  asm volatile("cp.async.wait_group 2;" ::: "memory")

__device__ __forceinline__ void ldm_x4(uint32_t* r, uint32_t addr) {
    asm volatile("ldmatrix.sync.aligned.m8n8.x4.shared.b16 {%0,%1,%2,%3}, [%4];"
                 : "=r"(r[0]), "=r"(r[1]), "=r"(r[2]), "=r"(r[3]) : "r"(addr));
}

__device__ __forceinline__ void mma16816(float* c, const uint32_t* a,
                                         uint32_t b0, uint32_t b1) {
    asm volatile(
        "mma.sync.aligned.m16n8k16.row.col.f32.f16.f16.f32 "
        "{%0,%1,%2,%3}, {%4,%5,%6,%7}, {%8,%9}, {%0,%1,%2,%3};"
        : "+f"(c[0]), "+f"(c[1]), "+f"(c[2]), "+f"(c[3])
        : "r"(a[0]), "r"(a[1]), "r"(a[2]), "r"(a[3]), "r"(b0), "r"(b1));
}

// ---------------- K0: precompute A0, Bc + zero pad rows --------------------------
__global__ void precompute_kernel(const float* __restrict__ Lre,
                                  const float* __restrict__ Lim,
                                  const float* __restrict__ logstep) {
    int c = threadIdx.x;
    int h = c >> 5;
    float st = expf(logstep[h]);
    float lr = Lre[c], li = Lim[c];
    float zr = lr * st, zi = li * st;
    float e  = expf(zr);
    float a0r = e * cosf(zi);
    float a0i = e * sinf(zi);
    float nr = a0r - 1.0f, ni = a0i;
    float inv = 1.0f / (lr * lr + li * li);
    g_A0[c] = make_float2(a0r, a0i);
    g_Bc[c] = make_float2((nr * lr + ni * li) * inv, (ni * lr - nr * li) * inv);

    __half z = __float2half(0.0f);
    g_Apad[0 * EPH + c] = z;
    g_Apad[(L + 1) * EPH + c] = z;
    g_Apad[(L + 2) * EPH + c] = z;
}

// ---------------- K1: B_proj (fp16 into padded buf) ; Lam = silu(x@Wl) -----------
__global__ __launch_bounds__(256) void proj_kernel(const float* __restrict__ x,
                                                   const float* __restrict__ Wb,
                                                   const float* __restrict__ bb,
                                                   const float* __restrict__ Wl,
                                                   const float* __restrict__ bl) {
    __shared__ float xsm[32][33];
    int lb = blockIdx.x * 32;
    int t  = threadIdx.x;
    for (int i = t; i < 32 * 32; i += 256) {
        int r = i >> 5, h = i & 31;
        xsm[r][h] = x[(lb + r) * H + h];
    }
    __syncthreads();

    for (int j = 0; j < 4; j++) {
        int o = t + j * 256;
        {
            float wcol[32];
            #pragma unroll
            for (int h = 0; h < 32; h++) wcol[h] = Wb[h * EPH + o];
            float bv = bb[o];
            for (int r = 0; r < 32; r++) {
                float acc = bv;
                #pragma unroll
                for (int h = 0; h < 32; h++) acc += xsm[r][h] * wcol[h];
                g_Apad[(lb + r + 1) * EPH + o] = __float2half(acc);
            }
        }
        {
            float wcol[32];
            #pragma unroll
            for (int h = 0; h < 32; h++) wcol[h] = Wl[h * EPH + o];
            float bv = bl[o];
            for (int r = 0; r < 32; r++) {
                float acc = bv;
                #pragma unroll
                for (int h = 0; h < 32; h++) acc += xsm[r][h] * wcol[h];
                g_Lam[(lb + r) * EPH + o] = siluf(acc);
            }
        }
    }
}

// ---------------- K1b: transpose conv weights to [o][kk] fp16 --------------------
__global__ __launch_bounds__(256) void wtrans_kernel(const float* __restrict__ cw) {
    __shared__ float tile[32][33];
    int k0 = blockIdx.x * 32;
    int o0 = blockIdx.y * 32;
    int t = threadIdx.x;
    int r = t >> 5, c = t & 31;
    #pragma unroll
    for (int rr = r; rr < 32; rr += 8)
        tile[rr][c] = cw[(size_t)(k0 + rr) * EPH + o0 + c];
    __syncthreads();
    #pragma unroll
    for (int rr = r; rr < 32; rr += 8) {
        float v = tile[c][rr];
        size_t idx = (size_t)(o0 + rr) * KTOT + k0 + c;
        g_WT[idx] = __float2half(v);
    }
}

// ---------------- K2: conv GEMM via mma.sync fp16 (single product) ---------------
// CTA tile 128(m=l) x 128(n=o), BK=32, 8 warps (4 m x 2 n), warp tile 32x64.
// 4-stage cp.async pipeline, 2 CTAs/SM.
#define GM 128
#define GN 128
#define GK 32
#define NCHUNK (KTOT / GK)        // 128
#define ROWB 80                   // smem row stride bytes (32 fp16 = 64B + pad)
#define TILE_B (128 * ROWB)       // 10240
#define BUF_B (2 * TILE_B)        // A, W = 20480
#define STAGES 4
#define CONV_SMEM (STAGES * BUF_B)  // 81920 -> 2 CTAs/SM

__global__ __launch_bounds__(256, 2)
void conv_mma_kernel(const float* __restrict__ cb) {
    extern __shared__ char smem[];
    uint32_t sbase = smem_u32(smem);
    int t = threadIdx.x;
    int lane = t & 31;
    int wid = t >> 5;
    int warp_m = wid & 3;         // 4 warps in m
    int warp_n = wid >> 2;        // 2 warps in n
    int lb = blockIdx.x * GM;
    int nb = blockIdx.y * GN;

    float acc[2][8][4];
    #pragma unroll
    for (int i = 0; i < 2; i++)
        #pragma unroll
        for (int j = 0; j < 8; j++)
            #pragma unroll
            for (int k = 0; k < 4; k++) acc[i][j][k] = 0.0f;

    // load mapping: thread t -> row = t>>1, half = t&1 (two 16B chunks)
    int lrow = t >> 1;
    int lhalf = t & 1;
    uint32_t dpos = lrow * ROWB + lhalf * 32;

    auto issue = [&](int kc) {
        uint32_t base = sbase + (kc & 3) * BUF_B;
        int kg = kc * GK;
        int tap = kg >> 10;
        int i0 = kg & 1023;
        {
            size_t go = (size_t)(lb + lrow + tap) * EPH + i0 + lhalf * 16;
            const char* sp = (const char*)(g_Apad + go);
            CP_ASYNC16(base + dpos,      sp);
            CP_ASYNC16(base + dpos + 16, sp + 16);
        }
        {
            size_t go = (size_t)(nb + lrow) * KTOT + kg + lhalf * 16;
            const char* sw = (const char*)(g_WT + go);
            CP_ASYNC16(base + TILE_B + dpos,      sw);
            CP_ASYNC16(base + TILE_B + dpos + 16, sw + 16);
        }
    };

    // ldmatrix lane mapping
    int lr8 = lane & 7;
    int lsel = lane >> 3;             // 0..3
    int lmn = (lsel & 1) * 8 + lr8;   // row within 16
    int lk8 = (lsel >> 1) * 8;        // k offset 0/8

    issue(0); CP_COMMIT();
    issue(1); CP_COMMIT();
    issue(2); CP_COMMIT();

    for (int kc = 0; kc < NCHUNK; kc++) {
        CP_WAIT2();
        __syncthreads();
        if (kc + 3 < NCHUNK) issue(kc + 3);
        CP_COMMIT();

        uint32_t base = sbase + (kc & 3) * BUF_B;
        uint32_t Ah = base;
        uint32_t Wt = base + TILE_B;

        #pragma unroll
        for (int ks = 0; ks < 2; ks++) {
            int kbyte = (ks * 16 + lk8) * 2;
            uint32_t ah[2][4];
            #pragma unroll
            for (int im = 0; im < 2; im++) {
                uint32_t ro = (warp_m * 32 + im * 16 + lmn) * ROWB + kbyte;
                ldm_x4(ah[im], Ah + ro);
            }
            uint32_t w[4][4];
            #pragma unroll
            for (int in4 = 0; in4 < 4; in4++) {
                uint32_t ro = (warp_n * 64 + in4 * 16 + lmn) * ROWB + kbyte;
                ldm_x4(w[in4], Wt + ro);
            }
            #pragma unroll
            for (int in4 = 0; in4 < 4; in4++)
                #pragma unroll
                for (int im = 0; im < 2; im++) {
                    mma16816(acc[im][in4 * 2 + 0], ah[im], w[in4][0], w[in4][2]);
                    mma16816(acc[im][in4 * 2 + 1], ah[im], w[in4][1], w[in4][3]);
                }
        }
    }

    // epilogue: bias + silu, write fp32
    int gid = lane >> 2;
    int tig = lane & 3;
    #pragma unroll
    for (int im = 0; im < 2; im++) {
        int r0 = lb + warp_m * 32 + im * 16 + gid;
        #pragma unroll
        for (int j = 0; j < 8; j++) {
            int col = nb + warp_n * 64 + j * 8 + tig * 2;
            float b0 = cb[col], b1 = cb[col + 1];
            g_Bact[(size_t)r0 * EPH + col]           = siluf(acc[im][j][0] + b0);
            g_Bact[(size_t)r0 * EPH + col + 1]       = siluf(acc[im][j][1] + b1);
            g_Bact[(size_t)(r0 + 8) * EPH + col]     = siluf(acc[im][j][2] + b0);
            g_Bact[(size_t)(r0 + 8) * EPH + col + 1] = siluf(acc[im][j][3] + b1);
        }
    }
}

// ---------------- K3: elementwise A / Bu (high parallelism) ----------------------
__global__ __launch_bounds__(1024) void elemwise_kernel(const float* __restrict__ B) {
    int l = blockIdx.x;
    int c = threadIdx.x;
    int idx = l * NCH + c;
    float lam = g_Lam[idx];
    float ba  = g_Bact[idx];
    float2 a0 = g_A0[c];
    float2 bc = g_Bc[c];

    float zr = a0.x + lam;
    float zi = a0.y;
    float e  = expf(zr);
    float wr = 1.0f + e * cosf(zi);
    float wi = e * sinf(zi);
    float Ar = 0.5f * logf(wr * wr + wi * wi);
    float Ai = atan2f(wi, wr);

    int ep = c & 31;
    float br = B[l * (2 * EP) + ep * 2 + 0];
    float bi = B[l * (2 * EP) + ep * 2 + 1];
    float bur = (bc.x * br - bc.y * bi) * ba;
    float bui = (bc.x * bi + bc.y * br) * ba;

    g_A [idx] = make_float2(Ar, Ai);
    g_Bu[idx] = make_float2(bur, bui);
}

// ---------------- K4/K5/K6: chunked complex scan ---------------------------------
__global__ __launch_bounds__(256) void scan_p1_kernel() {
    int t = blockIdx.x * blockDim.x + threadIdx.x;
    int c = t & (NCH - 1);
    int ch = t >> 10;
    int base = ch * CHUNK_LEN;
    float Pr = 1.0f, Pi = 0.0f, sr = 0.0f, si = 0.0f;
    #pragma unroll 4
    for (int i = 0; i < CHUNK_LEN; i++) {
        float2 a = g_A [(base + i) * NCH + c];
        float2 b = g_Bu[(base + i) * NCH + c];
        float nsr = a.x * sr - a.y * si + b.x;
        float nsi = a.x * si + a.y * sr + b.y;
        sr = nsr; si = nsi;
        float npr = a.x * Pr - a.y * Pi;
        float npi = a.x * Pi + a.y * Pr;
        Pr = npr; Pi = npi;
    }
    g_agg[ch * NCH + c] = make_float4(Pr, Pi, sr, si);
}

__global__ __launch_bounds__(1024) void scan_p2_kernel() {
    int c = threadIdx.x;
    float cr = 0.0f, ci = 0.0f;
    #pragma unroll
    for (int ch = 0; ch < CHUNKS; ch++) {
        g_carry[ch * NCH + c] = make_float2(cr, ci);
        float4 g = g_agg[ch * NCH + c];
        float nr = g.x * cr - g.y * ci + g.z;
        float ni = g.x * ci + g.y * cr + g.w;
        cr = nr; ci = ni;
    }
}

__global__ __launch_bounds__(256) void scan_p3_kernel() {
    int t = blockIdx.x * blockDim.x + threadIdx.x;
    int c = t & (NCH - 1);
    int ch = t >> 10;
    int base = ch * CHUNK_LEN;
    float2 st = g_carry[ch * NCH + c];
    float xr = st.x, xi = st.y;
    #pragma unroll 4
    for (int i = 0; i < CHUNK_LEN; i++) {
        float2 a = g_A [(base + i) * NCH + c];
        float2 b = g_Bu[(base + i) * NCH + c];
        float nxr = a.x * xr - a.y * xi + b.x;
        float nxi = a.x * xi + a.y * xr + b.y;
        xr = nxr; xi = nxi;
        g_xs[(base + i) * NCH + c] = make_float2(xr, xi);
    }
}

// ---------------- K7: ys ---------------------------------------------------------
__global__ __launch_bounds__(256) void ys_kernel(const float* __restrict__ C) {
    int t = threadIdx.x;
    int lane = t & 31;
    int w = t >> 5;
    int l = blockIdx.x * 8 + w;
    const float2* xs = g_xs + (size_t)l * NCH;
    float acc = 0.0f;
    #pragma unroll
    for (int p = 0; p < 32; p++) {
        float cr = C[l * (2 * EP) + p * 2 + 0];
        float ci = C[l * (2 * EP) + p * 2 + 1];
        float2 v = xs[p * 32 + lane];
        acc += cr * v.x - ci * v.y;
    }
    g_ys[l * H + lane] = acc;
}

// ---------------- K8: gating + output projection ---------------------------------
__global__ __launch_bounds__(256) void final_kernel(const float* __restrict__ x,
                                                    const float* __restrict__ Wg,
                                                    const float* __restrict__ bg,
                                                    const float* __restrict__ Wd,
                                                    const float* __restrict__ bd,
                                                    const float* __restrict__ Wo,
                                                    const float* __restrict__ bo,
                                                    float* __restrict__ out) {
    __shared__ float sWg[H * H], sWo[H * H];
    __shared__ float sWd[H], sbg[H], sbo[H];
    __shared__ float sx[8][H], sht[8][H];
    int t = threadIdx.x;
    for (int i = t; i < H * H; i += 256) { sWg[i] = Wg[i]; sWo[i] = Wo[i]; }
    if (t < H) { sWd[t] = Wd[t]; sbg[t] = bg[t]; sbo[t] = bo[t]; }
    int lane = t & 31;
    int w = t >> 5;
    int l = blockIdx.x * 8 + w;
    sx[w][lane] = x[l * H + lane];
    __syncthreads();

    float xg = 0.0f, xd = 0.0f;
    #pragma unroll
    for (int h = 0; h < H; h++) {
        float xv = sx[w][h];
        xg += xv * sWg[h * H + lane];
        xd += xv * sWd[h];
    }
    float gt = siluf(xg + sbg[lane]);
    float d  = log1pf(expf(xd + bd[0]));
    float ysv = g_ys[l * H + lane];
    float xv  = sx[w][lane];
    float ht = (1.0f - gt) * (ysv + d * xv) + gt * xv;
    sht[w][lane] = ht;
    __syncwarp();

    float o = 0.0f;
    #pragma unroll
    for (int h = 0; h < H; h++) o += sht[w][h] * sWo[h * H + lane];
    out[l * H + lane] = o + sbo[lane];
}

// ---------------- launcher -------------------------------------------------------
extern "C" void kernel_launch(void* const* d_in, const int* in_sizes, int n_in,
                              void* d_out, int out_size) {
    const float* x       = (const float*)d_in[0];
    const float* Lre     = (const float*)d_in[1];
    const float* Lim     = (const float*)d_in[2];
    const float* B       = (const float*)d_in[3];
    const float* C       = (const float*)d_in[4];
    const float* logstep = (const float*)d_in[5];
    const float* Wb      = (const float*)d_in[6];
    const float* bb      = (const float*)d_in[7];
    const float* Wl      = (const float*)d_in[8];
    const float* bl      = (const float*)d_in[9];
    const float* cw      = (const float*)d_in[10];
    const float* cb      = (const float*)d_in[11];
    const float* Wg      = (const float*)d_in[12];
    const float* bg      = (const float*)d_in[13];
    const float* Wd      = (const float*)d_in[14];
    const float* bd      = (const float*)d_in[15];
    const float* Wo      = (const float*)d_in[16];
    const float* bo      = (const float*)d_in[17];
    float* out = (float*)d_out;

    static bool attr_set = false;
    if (!attr_set) {
        cudaFuncSetAttribute(conv_mma_kernel,
                             cudaFuncAttributeMaxDynamicSharedMemorySize, CONV_SMEM);
        attr_set = true;
    }

    // launch order keeps conv_mma_kernel at captured-profile index 3
    precompute_kernel<<<1, 1024>>>(Lre, Lim, logstep);
    proj_kernel<<<L / 32, 256>>>(x, Wb, bb, Wl, bl);

    dim3 wgrid(KTOT / 32, EPH / 32);          // (128, 32)
    wtrans_kernel<<<wgrid, 256>>>(cw);

    dim3 cgrid(L / GM, EPH / GN);             // (32, 8) = 256 CTAs
    conv_mma_kernel<<<cgrid, 256, CONV_SMEM>>>(cb);

    elemwise_kernel<<<L, 1024>>>(B);

    scan_p1_kernel<<<(CHUNKS * NCH) / 256, 256>>>();
    scan_p2_kernel<<<1, 1024>>>();
    scan_p3_kernel<<<(CHUNKS * NCH) / 256, 256>>>();

    ys_kernel<<<L / 8, 256>>>(C);
    final_kernel<<<L / 8, 256>>>(x, Wg, bg, Wd, bd, Wo, bo, out);
}

// round 10
// speedup vs baseline: 2.3998x; 1.1974x over previous
#include <cuda_runtime.h>
#include <cuda_fp16.h>
#include <math.h>
#include <stdint.h>

// Problem constants
#define L 4096
#define H 32
#define EP 32
#define EPH 1024
#define KTAP 4
#define NCH 1024
#define CHUNKS 64
#define CHUNK_LEN 64
#define KTOT 4096          // effective GEMM K = KTAP * EPH

// ---------------- scratch (device globals) ----------------
__device__ __half g_Apad[(L + 3) * EPH];     // padded tap-shift A, fp16
__device__ __half g_WT  [EPH * KTOT];        // conv weights transposed [o][kk], fp16
__device__ float  g_Lam  [L * EPH];
__device__ float  g_Bact [L * EPH];
__device__ float  g_ys   [L * H];
__device__ float4 g_agg  [CHUNKS * NCH];
__device__ float2 g_carry[CHUNKS * NCH];
__device__ float4 g_cA   [NCH];   // (a0x, cos(a0y), sin(a0y), 0)
__device__ float2 g_cB   [NCH];   // Bc complex

__device__ __forceinline__ float siluf(float v) {
    return v / (1.0f + expf(-v));
}

__device__ __forceinline__ uint32_t smem_u32(const void* p) {
    uint32_t a;
    asm("{ .reg .u64 t; cvta.to.shared.u64 t, %1; cvt.u32.u64 %0, t; }" : "=r"(a) : "l"(p));
    return a;
}

#define CP_ASYNC16(dst, src) \
    asm volatile("cp.async.cg.shared.global [%0], [%1], 16;" :: "r"(dst), "l"(src))
#define CP_COMMIT() asm volatile("cp.async.commit_group;" ::: "memory")
#define CP_WAIT2()  asm volatile("cp.async.wait_group 2;" ::: "memory")

__device__ __forceinline__ void ldm_x4(uint32_t* r, uint32_t addr) {
    asm volatile("ldmatrix.sync.aligned.m8n8.x4.shared.b16 {%0,%1,%2,%3}, [%4];"
                 : "=r"(r[0]), "=r"(r[1]), "=r"(r[2]), "=r"(r[3]) : "r"(addr));
}

__device__ __forceinline__ void mma16816(float* c, const uint32_t* a,
                                         uint32_t b0, uint32_t b1) {
    asm volatile(
        "mma.sync.aligned.m16n8k16.row.col.f32.f16.f16.f32 "
        "{%0,%1,%2,%3}, {%4,%5,%6,%7}, {%8,%9}, {%0,%1,%2,%3};"
        : "+f"(c[0]), "+f"(c[1]), "+f"(c[2]), "+f"(c[3])
        : "r"(a[0]), "r"(a[1]), "r"(a[2]), "r"(a[3]), "r"(b0), "r"(b1));
}

// fast elementwise recompute: A = log(1+exp(A0+lam)) (complex), Bu = Bc*Bt*ba
// |wi/wr| small by input ranges (e <= ~1.6, cz >= ~0.93 => wr >= 1, |r| <= ~0.4)
__device__ __forceinline__ void compute_ABu(float lam, float ba, float br, float bi,
                                            float a0x, float cz, float sz,
                                            float bcx, float bcy,
                                            float& Ar, float& Ai,
                                            float& bur, float& bui) {
    float e  = __expf(a0x + lam);
    float wr = fmaf(e, cz, 1.0f);
    float wi = e * sz;
    Ar = 0.5f * __logf(fmaf(wr, wr, wi * wi));
    float r  = __fdividef(wi, wr);
    float r2 = r * r;
    Ai = r * fmaf(r2, fmaf(r2, fmaf(r2, fmaf(r2, fmaf(r2,
            -0.0909090909f, 0.1111111111f), -0.1428571429f),
             0.2f), -0.3333333333f), 1.0f);
    bur = (bcx * br - bcy * bi) * ba;
    bui = (bcx * bi + bcy * br) * ba;
}

// ---------------- K0: precompute constants + zero pad rows -----------------------
__global__ void precompute_kernel(const float* __restrict__ Lre,
                                  const float* __restrict__ Lim,
                                  const float* __restrict__ logstep) {
    int c = threadIdx.x;
    int h = c >> 5;
    float st = expf(logstep[h]);
    float lr = Lre[c], li = Lim[c];
    float zr = lr * st, zi = li * st;
    float e  = expf(zr);
    float a0r = e * cosf(zi);
    float a0i = e * sinf(zi);
    float nr = a0r - 1.0f, ni = a0i;
    float inv = 1.0f / (lr * lr + li * li);
    g_cA[c] = make_float4(a0r, cosf(a0i), sinf(a0i), 0.0f);
    g_cB[c] = make_float2((nr * lr + ni * li) * inv, (ni * lr - nr * li) * inv);

    __half z = __float2half(0.0f);
    g_Apad[0 * EPH + c] = z;
    g_Apad[(L + 1) * EPH + c] = z;
    g_Apad[(L + 2) * EPH + c] = z;
}

// ---------------- K1: B_proj (fp16 into padded buf) ; Lam = silu(x@Wl) -----------
__global__ __launch_bounds__(256) void proj_kernel(const float* __restrict__ x,
                                                   const float* __restrict__ Wb,
                                                   const float* __restrict__ bb,
                                                   const float* __restrict__ Wl,
                                                   const float* __restrict__ bl) {
    __shared__ float xsm[32][33];
    int lb = blockIdx.x * 32;
    int t  = threadIdx.x;
    for (int i = t; i < 32 * 32; i += 256) {
        int r = i >> 5, h = i & 31;
        xsm[r][h] = x[(lb + r) * H + h];
    }
    __syncthreads();

    for (int j = 0; j < 4; j++) {
        int o = t + j * 256;
        {
            float wcol[32];
            #pragma unroll
            for (int h = 0; h < 32; h++) wcol[h] = Wb[h * EPH + o];
            float bv = bb[o];
            for (int r = 0; r < 32; r++) {
                float acc = bv;
                #pragma unroll
                for (int h = 0; h < 32; h++) acc += xsm[r][h] * wcol[h];
                g_Apad[(lb + r + 1) * EPH + o] = __float2half(acc);
            }
        }
        {
            float wcol[32];
            #pragma unroll
            for (int h = 0; h < 32; h++) wcol[h] = Wl[h * EPH + o];
            float bv = bl[o];
            for (int r = 0; r < 32; r++) {
                float acc = bv;
                #pragma unroll
                for (int h = 0; h < 32; h++) acc += xsm[r][h] * wcol[h];
                g_Lam[(lb + r) * EPH + o] = siluf(acc);
            }
        }
    }
}

// ---------------- K1b: transpose conv weights to [o][kk] fp16 --------------------
__global__ __launch_bounds__(256) void wtrans_kernel(const float* __restrict__ cw) {
    __shared__ float tile[32][33];
    int k0 = blockIdx.x * 32;
    int o0 = blockIdx.y * 32;
    int t = threadIdx.x;
    int r = t >> 5, c = t & 31;
    #pragma unroll
    for (int rr = r; rr < 32; rr += 8)
        tile[rr][c] = cw[(size_t)(k0 + rr) * EPH + o0 + c];
    __syncthreads();
    #pragma unroll
    for (int rr = r; rr < 32; rr += 8) {
        float v = tile[c][rr];
        size_t idx = (size_t)(o0 + rr) * KTOT + k0 + c;
        g_WT[idx] = __float2half(v);
    }
}

// ---------------- K2: conv GEMM via mma.sync fp16 (single product) ---------------
// R8 winner config: 128x128 tile, 8 warps, 4-stage cp.async, 2 CTA/SM
#define GM 128
#define GN 128
#define GK 32
#define NCHUNK (KTOT / GK)        // 128
#define ROWB 80
#define TILE_B (128 * ROWB)
#define BUF_B (2 * TILE_B)
#define STAGES 4
#define CONV_SMEM (STAGES * BUF_B)  // 81920

__global__ __launch_bounds__(256, 2)
void conv_mma_kernel(const float* __restrict__ cb) {
    extern __shared__ char smem[];
    uint32_t sbase = smem_u32(smem);
    int t = threadIdx.x;
    int lane = t & 31;
    int wid = t >> 5;
    int warp_m = wid & 3;
    int warp_n = wid >> 2;
    int lb = blockIdx.x * GM;
    int nb = blockIdx.y * GN;

    float acc[2][8][4];
    #pragma unroll
    for (int i = 0; i < 2; i++)
        #pragma unroll
        for (int j = 0; j < 8; j++)
            #pragma unroll
            for (int k = 0; k < 4; k++) acc[i][j][k] = 0.0f;

    int lrow = t >> 1;
    int lhalf = t & 1;
    uint32_t dpos = lrow * ROWB + lhalf * 32;

    auto issue = [&](int kc) {
        uint32_t base = sbase + (kc & 3) * BUF_B;
        int kg = kc * GK;
        int tap = kg >> 10;
        int i0 = kg & 1023;
        {
            size_t go = (size_t)(lb + lrow + tap) * EPH + i0 + lhalf * 16;
            const char* sp = (const char*)(g_Apad + go);
            CP_ASYNC16(base + dpos,      sp);
            CP_ASYNC16(base + dpos + 16, sp + 16);
        }
        {
            size_t go = (size_t)(nb + lrow) * KTOT + kg + lhalf * 16;
            const char* sw = (const char*)(g_WT + go);
            CP_ASYNC16(base + TILE_B + dpos,      sw);
            CP_ASYNC16(base + TILE_B + dpos + 16, sw + 16);
        }
    };

    int lr8 = lane & 7;
    int lsel = lane >> 3;
    int lmn = (lsel & 1) * 8 + lr8;
    int lk8 = (lsel >> 1) * 8;

    issue(0); CP_COMMIT();
    issue(1); CP_COMMIT();
    issue(2); CP_COMMIT();

    for (int kc = 0; kc < NCHUNK; kc++) {
        CP_WAIT2();
        __syncthreads();
        if (kc + 3 < NCHUNK) issue(kc + 3);
        CP_COMMIT();

        uint32_t base = sbase + (kc & 3) * BUF_B;
        uint32_t Ah = base;
        uint32_t Wt = base + TILE_B;

        #pragma unroll
        for (int ks = 0; ks < 2; ks++) {
            int kbyte = (ks * 16 + lk8) * 2;
            uint32_t ah[2][4];
            #pragma unroll
            for (int im = 0; im < 2; im++) {
                uint32_t ro = (warp_m * 32 + im * 16 + lmn) * ROWB + kbyte;
                ldm_x4(ah[im], Ah + ro);
            }
            uint32_t w[4][4];
            #pragma unroll
            for (int in4 = 0; in4 < 4; in4++) {
                uint32_t ro = (warp_n * 64 + in4 * 16 + lmn) * ROWB + kbyte;
                ldm_x4(w[in4], Wt + ro);
            }
            #pragma unroll
            for (int in4 = 0; in4 < 4; in4++)
                #pragma unroll
                for (int im = 0; im < 2; im++) {
                    mma16816(acc[im][in4 * 2 + 0], ah[im], w[in4][0], w[in4][2]);
                    mma16816(acc[im][in4 * 2 + 1], ah[im], w[in4][1], w[in4][3]);
                }
        }
    }

    int gid = lane >> 2;
    int tig = lane & 3;
    #pragma unroll
    for (int im = 0; im < 2; im++) {
        int r0 = lb + warp_m * 32 + im * 16 + gid;
        #pragma unroll
        for (int j = 0; j < 8; j++) {
            int col = nb + warp_n * 64 + j * 8 + tig * 2;
            float b0 = cb[col], b1 = cb[col + 1];
            g_Bact[(size_t)r0 * EPH + col]           = siluf(acc[im][j][0] + b0);
            g_Bact[(size_t)r0 * EPH + col + 1]       = siluf(acc[im][j][1] + b1);
            g_Bact[(size_t)(r0 + 8) * EPH + col]     = siluf(acc[im][j][2] + b0);
            g_Bact[(size_t)(r0 + 8) * EPH + col + 1] = siluf(acc[im][j][3] + b1);
        }
    }
}

// ---------------- K3: scan pass 1 (recompute A/Bu inline) ------------------------
// channel c = h*32 + ep : B index uses ep = c & 31
__global__ __launch_bounds__(256) void scan_p1_kernel(const float* __restrict__ B) {
    int t = blockIdx.x * blockDim.x + threadIdx.x;   // CHUNKS*NCH = 65536
    int c = t & (NCH - 1);
    int ch = t >> 10;
    int base = ch * CHUNK_LEN;
    int ep = c & 31;

    float4 cA = g_cA[c];
    float2 cB = g_cB[c];

    float Pr = 1.0f, Pi = 0.0f, sr = 0.0f, si = 0.0f;
    for (int i = 0; i < CHUNK_LEN; i++) {
        int l = base + i;
        int idx = l * NCH + c;
        float lam = g_Lam[idx];
        float ba  = g_Bact[idx];
        float br = B[l * 64 + ep * 2 + 0];
        float bi = B[l * 64 + ep * 2 + 1];
        float Ar, Ai, bur, bui;
        compute_ABu(lam, ba, br, bi, cA.x, cA.y, cA.z, cB.x, cB.y, Ar, Ai, bur, bui);

        float nsr = Ar * sr - Ai * si + bur;
        float nsi = Ar * si + Ai * sr + bui;
        sr = nsr; si = nsi;
        float npr = Ar * Pr - Ai * Pi;
        float npi = Ar * Pi + Ai * Pr;
        Pr = npr; Pi = npi;
    }
    g_agg[ch * NCH + c] = make_float4(Pr, Pi, sr, si);
}

// ---------------- K4: scan pass 2 (serial over chunks) ---------------------------
__global__ __launch_bounds__(1024) void scan_p2_kernel() {
    int c = threadIdx.x;
    float cr = 0.0f, ci = 0.0f;
    #pragma unroll
    for (int ch = 0; ch < CHUNKS; ch++) {
        g_carry[ch * NCH + c] = make_float2(cr, ci);
        float4 g = g_agg[ch * NCH + c];
        float nr = g.x * cr - g.y * ci + g.z;
        float ni = g.x * ci + g.y * cr + g.w;
        cr = nr; ci = ni;
    }
}

// ---------------- K5: scan pass 3 (recompute A/Bu, fused ys via atomics) ---------
// B index: ep = c & 31.  C/ys index (reference reshape (L,EP,H)): p = c>>5, j = c&31.
__global__ __launch_bounds__(256) void scan_p3_kernel(const float* __restrict__ B,
                                                      const float* __restrict__ C) {
    int t = blockIdx.x * blockDim.x + threadIdx.x;
    int c = t & (NCH - 1);
    int ch = t >> 10;
    int base = ch * CHUNK_LEN;
    int ep = c & 31;
    int p = c >> 5;
    int j = c & 31;

    float4 cA = g_cA[c];
    float2 cB = g_cB[c];

    float2 st = g_carry[ch * NCH + c];
    float xr = st.x, xi = st.y;
    for (int i = 0; i < CHUNK_LEN; i++) {
        int l = base + i;
        int idx = l * NCH + c;
        float lam = g_Lam[idx];
        float ba  = g_Bact[idx];
        float br = B[l * 64 + ep * 2 + 0];
        float bi = B[l * 64 + ep * 2 + 1];
        float Ar, Ai, bur, bui;
        compute_ABu(lam, ba, br, bi, cA.x, cA.y, cA.z, cB.x, cB.y, Ar, Ai, bur, bui);

        float nxr = Ar * xr - Ai * xi + bur;
        float nxi = Ar * xi + Ai * xr + bui;
        xr = nxr; xi = nxi;

        float cr = C[l * 64 + p * 2 + 0];
        float ci = C[l * 64 + p * 2 + 1];
        atomicAdd(&g_ys[l * H + j], cr * xr - ci * xi);
    }
}

// ---------------- K8: gating + output projection ---------------------------------
__global__ __launch_bounds__(256) void final_kernel(const float* __restrict__ x,
                                                    const float* __restrict__ Wg,
                                                    const float* __restrict__ bg,
                                                    const float* __restrict__ Wd,
                                                    const float* __restrict__ bd,
                                                    const float* __restrict__ Wo,
                                                    const float* __restrict__ bo,
                                                    float* __restrict__ out) {
    __shared__ float sWg[H * H], sWo[H * H];
    __shared__ float sWd[H], sbg[H], sbo[H];
    __shared__ float sx[8][H], sht[8][H];
    int t = threadIdx.x;
    for (int i = t; i < H * H; i += 256) { sWg[i] = Wg[i]; sWo[i] = Wo[i]; }
    if (t < H) { sWd[t] = Wd[t]; sbg[t] = bg[t]; sbo[t] = bo[t]; }
    int lane = t & 31;
    int w = t >> 5;
    int l = blockIdx.x * 8 + w;
    sx[w][lane] = x[l * H + lane];
    __syncthreads();

    float xg = 0.0f, xd = 0.0f;
    #pragma unroll
    for (int h = 0; h < H; h++) {
        float xv = sx[w][h];
        xg += xv * sWg[h * H + lane];
        xd += xv * sWd[h];
    }
    float gt = siluf(xg + sbg[lane]);
    float d  = log1pf(expf(xd + bd[0]));
    float ysv = g_ys[l * H + lane];
    float xv  = sx[w][lane];
    float ht = (1.0f - gt) * (ysv + d * xv) + gt * xv;
    sht[w][lane] = ht;
    __syncwarp();

    float o = 0.0f;
    #pragma unroll
    for (int h = 0; h < H; h++) o += sht[w][h] * sWo[h * H + lane];
    out[l * H + lane] = o + sbo[lane];
}

// ---------------- launcher -------------------------------------------------------
extern "C" void kernel_launch(void* const* d_in, const int* in_sizes, int n_in,
                              void* d_out, int out_size) {
    const float* x       = (const float*)d_in[0];
    const float* Lre     = (const float*)d_in[1];
    const float* Lim     = (const float*)d_in[2];
    const float* B       = (const float*)d_in[3];
    const float* C       = (const float*)d_in[4];
    const float* logstep = (const float*)d_in[5];
    const float* Wb      = (const float*)d_in[6];
    const float* bb      = (const float*)d_in[7];
    const float* Wl      = (const float*)d_in[8];
    const float* bl      = (const float*)d_in[9];
    const float* cw      = (const float*)d_in[10];
    const float* cb      = (const float*)d_in[11];
    const float* Wg      = (const float*)d_in[12];
    const float* bg      = (const float*)d_in[13];
    const float* Wd      = (const float*)d_in[14];
    const float* bd      = (const float*)d_in[15];
    const float* Wo      = (const float*)d_in[16];
    const float* bo      = (const float*)d_in[17];
    float* out = (float*)d_out;

    cudaFuncSetAttribute(conv_mma_kernel,
                         cudaFuncAttributeMaxDynamicSharedMemorySize, CONV_SMEM);

    void* ys_ptr = nullptr;
    cudaGetSymbolAddress(&ys_ptr, g_ys);
    cudaMemsetAsync(ys_ptr, 0, L * H * sizeof(float));

    precompute_kernel<<<1, 1024>>>(Lre, Lim, logstep);
    proj_kernel<<<L / 32, 256>>>(x, Wb, bb, Wl, bl);

    dim3 wgrid(KTOT / 32, EPH / 32);          // (128, 32)
    wtrans_kernel<<<wgrid, 256>>>(cw);

    dim3 cgrid(L / GM, EPH / GN);             // (32, 8) = 256 CTAs
    conv_mma_kernel<<<cgrid, 256, CONV_SMEM>>>(cb);

    scan_p1_kernel<<<(CHUNKS * NCH) / 256, 256>>>(B);
    scan_p2_kernel<<<1, 1024>>>();
    scan_p3_kernel<<<(CHUNKS * NCH) / 256, 256>>>(B, C);

    final_kernel<<<L / 8, 256>>>(x, Wg, bg, Wd, bd, Wo, bo, out);
}